// round 1
// baseline (speedup 1.0000x reference)
#include <cuda_runtime.h>
#include <cuda_bf16.h>
#include <stdint.h>

// ============================================================================
// ChaosLanguageModel: embed-mean -> 10-tick stochastic spiking -> readout
// Must replicate JAX threefry2x32 RNG bit-exactly (partitionable path,
// the default in modern JAX: split = foldlike, random_bits = out0 ^ out1).
// ============================================================================

#define EMBED 16
#define HIDDEN 64
#define TICKS 10
#define SEQLEN 200

// ---------------------------------------------------------------------------
// scratch (no allocation allowed)
// ---------------------------------------------------------------------------
__device__ float g_cur[16384 * HIDDEN];   // drive current per neuron
__device__ float g_spk[16384 * HIDDEN];   // fallback spike buffer

// ---------------------------------------------------------------------------
// threefry2x32 (JAX rotation schedule)
// ---------------------------------------------------------------------------
__device__ __forceinline__ void tf2x32_dev(uint32_t k0, uint32_t k1,
                                           uint32_t x0, uint32_t x1,
                                           uint32_t& o0, uint32_t& o1) {
    uint32_t k2 = k0 ^ k1 ^ 0x1BD11BDAu;
#define TF_RND(r) { x0 += x1; x1 = __funnelshift_l(x1, x1, (r)); x1 ^= x0; }
    x0 += k0; x1 += k1;
    TF_RND(13) TF_RND(15) TF_RND(26) TF_RND(6)
    x0 += k1; x1 += k2 + 1u;
    TF_RND(17) TF_RND(29) TF_RND(16) TF_RND(24)
    x0 += k2; x1 += k0 + 2u;
    TF_RND(13) TF_RND(15) TF_RND(26) TF_RND(6)
    x0 += k0; x1 += k1 + 3u;
    TF_RND(17) TF_RND(29) TF_RND(16) TF_RND(24)
    x0 += k1; x1 += k2 + 4u;
    TF_RND(13) TF_RND(15) TF_RND(26) TF_RND(6)
    x0 += k2; x1 += k0 + 5u;
#undef TF_RND
    o0 = x0; o1 = x1;
}

static inline uint32_t rotl_h(uint32_t x, int r) { return (x << r) | (x >> (32 - r)); }
static void tf2x32_host(uint32_t k0, uint32_t k1, uint32_t x0, uint32_t x1,
                        uint32_t* o0, uint32_t* o1) {
    uint32_t k2 = k0 ^ k1 ^ 0x1BD11BDAu;
#define TF_RND(r) { x0 += x1; x1 = rotl_h(x1, (r)); x1 ^= x0; }
    x0 += k0; x1 += k1;
    TF_RND(13) TF_RND(15) TF_RND(26) TF_RND(6)
    x0 += k1; x1 += k2 + 1u;
    TF_RND(17) TF_RND(29) TF_RND(16) TF_RND(24)
    x0 += k2; x1 += k0 + 2u;
    TF_RND(13) TF_RND(15) TF_RND(26) TF_RND(6)
    x0 += k0; x1 += k1 + 3u;
    TF_RND(17) TF_RND(29) TF_RND(16) TF_RND(24)
    x0 += k1; x1 += k2 + 4u;
    TF_RND(13) TF_RND(15) TF_RND(26) TF_RND(6)
    x0 += k2; x1 += k0 + 5u;
#undef TF_RND
    *o0 = x0; *o1 = x1;
}

// ---------------------------------------------------------------------------
// XLA erf_inv (f32, Giles polynomial) — matches XLA's elemental emitter.
// log1pf / sqrtf are libdevice == what XLA emits on GPU.
// ---------------------------------------------------------------------------
__device__ __forceinline__ float erfinv_xla(float x) {
    float t = __fmul_rn(x, x);
    float w = -log1pf(-t);
    float p;
    if (w < 5.0f) {
        w = __fsub_rn(w, 2.5f);
        p = 2.81022636e-08f;
        p = __fadd_rn(__fmul_rn(p, w),  3.43273939e-07f);
        p = __fadd_rn(__fmul_rn(p, w), -3.5233877e-06f);
        p = __fadd_rn(__fmul_rn(p, w), -4.39150654e-06f);
        p = __fadd_rn(__fmul_rn(p, w),  0.00021858087f);
        p = __fadd_rn(__fmul_rn(p, w), -0.00125372503f);
        p = __fadd_rn(__fmul_rn(p, w), -0.00417768164f);
        p = __fadd_rn(__fmul_rn(p, w),  0.246640727f);
        p = __fadd_rn(__fmul_rn(p, w),  1.50140941f);
    } else {
        w = __fsub_rn(__fsqrt_rn(w), 3.0f);
        p = -0.000200214257f;
        p = __fadd_rn(__fmul_rn(p, w),  0.000100950558f);
        p = __fadd_rn(__fmul_rn(p, w),  0.00134934322f);
        p = __fadd_rn(__fmul_rn(p, w), -0.00367342844f);
        p = __fadd_rn(__fmul_rn(p, w),  0.00573950773f);
        p = __fadd_rn(__fmul_rn(p, w), -0.0076224613f);
        p = __fadd_rn(__fmul_rn(p, w),  0.00943887047f);
        p = __fadd_rn(__fmul_rn(p, w),  1.00167406f);
        p = __fadd_rn(__fmul_rn(p, w),  2.83297682f);
    }
    return __fmul_rn(p, x);
}

// ---------------------------------------------------------------------------
// Phase A: masked mean embedding + input linear -> cur[B][64]
// One block (128 thr) per row. f64 accumulation to minimize deviation
// from XLA's own f32 reduction error.
// ---------------------------------------------------------------------------
__global__ void phaseA_kernel(const int* __restrict__ tokens,
                              const float* __restrict__ embed,
                              const float* __restrict__ Wc,
                              const float* __restrict__ bc,
                              float* __restrict__ cur, int L) {
    __shared__ int    stok[256];
    __shared__ double ssum[8][EMBED];
    __shared__ int    scnt[8];
    __shared__ float  savg[EMBED];

    int row = blockIdx.x;
    int tid = threadIdx.x;
    for (int j = tid; j < L; j += 128)
        stok[j] = tokens[(size_t)row * L + j];
    __syncthreads();

    int c = tid >> 4;       // chunk 0..7
    int e = tid & 15;       // embed dim
    int cs = (L + 7) / 8;
    int j0 = c * cs;
    int j1 = min(L, j0 + cs);
    double s = 0.0; int cnt = 0;
    for (int j = j0; j < j1; ++j) {
        int tk = stok[j];
        if (tk != 0) { s += (double)embed[(size_t)tk * EMBED + e]; cnt++; }
    }
    ssum[c][e] = s;
    if (e == 0) scnt[c] = cnt;
    __syncthreads();

    if (tid < EMBED) {
        double tot = 0.0; int cv = 0;
        #pragma unroll
        for (int k = 0; k < 8; k++) { tot += ssum[k][tid]; cv += scnt[k]; }
        float validf = fmaxf((float)cv, 1.0f);
        savg[tid] = __fdiv_rn((float)tot, validf);
    }
    __syncthreads();

    if (tid < HIDDEN) {
        double dd = 0.0;
        #pragma unroll
        for (int q = 0; q < EMBED; q++)
            dd += (double)savg[q] * (double)Wc[tid * EMBED + q];
        cur[(size_t)row * HIDDEN + tid] = __fadd_rn((float)dd, bc[tid]);
    }
}

// ---------------------------------------------------------------------------
// Phase B: 10-tick stochastic spiking recurrence. One thread per neuron.
// noise bits   = tf(kn_t, (0, i)).0 ^ .1
// fail bits    = tf(kf_t, (0, i)).0 ^ .1
// ---------------------------------------------------------------------------
struct KeysParam { uint32_t kn0[TICKS], kn1[TICKS], kf0[TICKS], kf1[TICKS]; };

__global__ void __launch_bounds__(256)
phaseB_kernel(const float* __restrict__ cur, float* __restrict__ spk_out,
              KeysParam K, int n, int use_global_fallback) {
    int i = blockIdx.x * blockDim.x + threadIdx.x;
    if (i >= n) return;
    float* outp = use_global_fallback ? g_spk : spk_out;

    float cu = cur[i];
    float v = 0.0f, rf = 0.0f, acc = 0.0f;
    uint32_t ui = (uint32_t)i;
    const float LO = -0.99999994f;   // nextafter(-1, 0) in f32

    #pragma unroll
    for (int t = 0; t < TICKS; t++) {
        uint32_t n0, n1, f0, f1;
        tf2x32_dev(K.kn0[t], K.kn1[t], 0u, ui, n0, n1);
        tf2x32_dev(K.kf0[t], K.kf1[t], 0u, ui, f0, f1);
        uint32_t nb = n0 ^ n1;
        uint32_t fb = f0 ^ f1;

        // jax.random.normal: u in [lo, 1), z = sqrt(2)*erfinv(u)
        float fr = __fsub_rn(__uint_as_float((nb >> 9) | 0x3f800000u), 1.0f);
        float u  = fmaxf(LO, __fadd_rn(__fmul_rn(fr, 2.0f), LO));
        float z  = erfinv_xla(u);
        float noise = __fmul_rn(0.01f, __fmul_rn(1.41421356237309515f, z));

        // v = v*(1-DECAY) + cur + noise   (left-to-right, no FMA)
        v = __fadd_rn(__fadd_rn(__fmul_rn(v, 0.98f), cu), noise);

        // fail uniform in [0,1): exact
        float uf = __fsub_rn(__uint_as_float((fb >> 9) | 0x3f800000u), 1.0f);
        bool fire = (__fsub_rn(v, rf) > 0.5f) && (uf >= 0.5f);
        float spike = fire ? 1.0f : 0.0f;
        v  = fire ? 0.0f : v;
        rf = __fadd_rn(__fmul_rn(rf, 0.95f), spike);
        acc = __fadd_rn(acc, spike);
    }
    outp[i] = __fdiv_rn(acc, 10.0f);
}

// ---------------------------------------------------------------------------
// Phase C: logits = avg_spikes @ Wr.T + br   (one warp per row)
// ---------------------------------------------------------------------------
__global__ void phaseC_kernel(const float* __restrict__ spk_in,
                              const float* __restrict__ Wr,
                              const float* __restrict__ br,
                              float* __restrict__ logits, int B,
                              int use_global_fallback) {
    const float* spk = use_global_fallback ? g_spk : spk_in;
    int gw   = (blockIdx.x * blockDim.x + threadIdx.x) >> 5;
    int lane = threadIdx.x & 31;
    if (gw >= B) return;
    float s0 = spk[gw * HIDDEN + lane];
    float s1 = spk[gw * HIDDEN + 32 + lane];
    #pragma unroll
    for (int cc = 0; cc < 4; cc++) {
        float p = __fadd_rn(__fmul_rn(s0, Wr[cc * HIDDEN + lane]),
                            __fmul_rn(s1, Wr[cc * HIDDEN + 32 + lane]));
        #pragma unroll
        for (int o = 16; o; o >>= 1)
            p = __fadd_rn(p, __shfl_xor_sync(0xffffffffu, p, o));
        if (lane == 0) logits[gw * 4 + cc] = __fadd_rn(p, br[cc]);
    }
}

// ---------------------------------------------------------------------------
// kernel_launch
// inputs: tokens(int32 B*L), embed(f32 50257*16), Wc(64*16), bc(64),
//         Wr(4*64), br(4)
// output: concat(logits[B,4].ravel(), avg_spikes[1,B,64].ravel())
// ---------------------------------------------------------------------------
extern "C" void kernel_launch(void* const* d_in, const int* in_sizes, int n_in,
                              void* d_out, int out_size) {
    const int*   tokens = (const int*)d_in[0];
    const float* embed  = (const float*)d_in[1];
    const float* Wc     = (const float*)d_in[2];
    const float* bc     = (const float*)d_in[3];
    const float* Wr     = (const float*)d_in[4];
    const float* br     = (const float*)d_in[5];

    int L = SEQLEN;
    int B = in_sizes[0] / L;
    int n = B * HIDDEN;

    // ---- derive per-tick keys on host (JAX partitionable path) ----
    // base key = jax.random.key(1) -> (0, 1)
    // keys[t]  = threefry((0,1), (0, t))           [foldlike split]
    // kn_t     = threefry(keys[t], (0, 0))
    // kf_t     = threefry(keys[t], (0, 1))
    KeysParam K;
    for (int t = 0; t < TICKS; t++) {
        uint32_t kt0, kt1;
        tf2x32_host(0u, 1u, 0u, (uint32_t)t, &kt0, &kt1);
        tf2x32_host(kt0, kt1, 0u, 0u, &K.kn0[t], &K.kn1[t]);
        tf2x32_host(kt0, kt1, 0u, 1u, &K.kf0[t], &K.kf1[t]);
    }

    float* out_f = (float*)d_out;
    int need = B * 4 + B * HIDDEN;
    int fallback = (out_size < need) ? 1 : 0;
    float* spk_region = fallback ? (float*)nullptr : (out_f + B * 4);

    // Phase A: cur
    {
        void* cur_ptr = nullptr;
        cudaGetSymbolAddress(&cur_ptr, g_cur);
        phaseA_kernel<<<B, 128>>>(tokens, embed, Wc, bc, (float*)cur_ptr, L);
        // Phase B
        phaseB_kernel<<<(n + 255) / 256, 256>>>((const float*)cur_ptr,
                                                spk_region, K, n, fallback);
        // Phase C
        int warps = B;
        phaseC_kernel<<<(warps * 32 + 255) / 256, 256>>>(spk_region, Wr, br,
                                                         out_f, B, fallback);
    }
}

// round 2
// speedup vs baseline: 2.8179x; 2.8179x over previous
#include <cuda_runtime.h>
#include <cuda_bf16.h>
#include <stdint.h>

// ============================================================================
// ChaosLanguageModel: embed-mean -> 10-tick stochastic spiking -> readout
// Replicates JAX threefry2x32 RNG bit-exactly (partitionable path).
// R2: phaseA rewritten warp-per-row, f32 ILP accumulation (was FP64-latency
// bound at 297us; gather floor is ~25us).
// ============================================================================

#define EMBED 16
#define HIDDEN 64
#define TICKS 10
#define SEQLEN 200

__device__ float g_cur[16384 * HIDDEN];   // drive current per neuron
__device__ float g_spk[16384 * HIDDEN];   // fallback spike buffer

// ---------------------------------------------------------------------------
// threefry2x32 (JAX rotation schedule)
// ---------------------------------------------------------------------------
__device__ __forceinline__ void tf2x32_dev(uint32_t k0, uint32_t k1,
                                           uint32_t x0, uint32_t x1,
                                           uint32_t& o0, uint32_t& o1) {
    uint32_t k2 = k0 ^ k1 ^ 0x1BD11BDAu;
#define TF_RND(r) { x0 += x1; x1 = __funnelshift_l(x1, x1, (r)); x1 ^= x0; }
    x0 += k0; x1 += k1;
    TF_RND(13) TF_RND(15) TF_RND(26) TF_RND(6)
    x0 += k1; x1 += k2 + 1u;
    TF_RND(17) TF_RND(29) TF_RND(16) TF_RND(24)
    x0 += k2; x1 += k0 + 2u;
    TF_RND(13) TF_RND(15) TF_RND(26) TF_RND(6)
    x0 += k0; x1 += k1 + 3u;
    TF_RND(17) TF_RND(29) TF_RND(16) TF_RND(24)
    x0 += k1; x1 += k2 + 4u;
    TF_RND(13) TF_RND(15) TF_RND(26) TF_RND(6)
    x0 += k2; x1 += k0 + 5u;
#undef TF_RND
    o0 = x0; o1 = x1;
}

static inline uint32_t rotl_h(uint32_t x, int r) { return (x << r) | (x >> (32 - r)); }
static void tf2x32_host(uint32_t k0, uint32_t k1, uint32_t x0, uint32_t x1,
                        uint32_t* o0, uint32_t* o1) {
    uint32_t k2 = k0 ^ k1 ^ 0x1BD11BDAu;
#define TF_RND(r) { x0 += x1; x1 = rotl_h(x1, (r)); x1 ^= x0; }
    x0 += k0; x1 += k1;
    TF_RND(13) TF_RND(15) TF_RND(26) TF_RND(6)
    x0 += k1; x1 += k2 + 1u;
    TF_RND(17) TF_RND(29) TF_RND(16) TF_RND(24)
    x0 += k2; x1 += k0 + 2u;
    TF_RND(13) TF_RND(15) TF_RND(26) TF_RND(6)
    x0 += k0; x1 += k1 + 3u;
    TF_RND(17) TF_RND(29) TF_RND(16) TF_RND(24)
    x0 += k1; x1 += k2 + 4u;
    TF_RND(13) TF_RND(15) TF_RND(26) TF_RND(6)
    x0 += k2; x1 += k0 + 5u;
#undef TF_RND
    *o0 = x0; *o1 = x1;
}

// ---------------------------------------------------------------------------
// XLA erf_inv (f32, Giles polynomial)
// ---------------------------------------------------------------------------
__device__ __forceinline__ float erfinv_xla(float x) {
    float t = __fmul_rn(x, x);
    float w = -log1pf(-t);
    float p;
    if (w < 5.0f) {
        w = __fsub_rn(w, 2.5f);
        p = 2.81022636e-08f;
        p = __fadd_rn(__fmul_rn(p, w),  3.43273939e-07f);
        p = __fadd_rn(__fmul_rn(p, w), -3.5233877e-06f);
        p = __fadd_rn(__fmul_rn(p, w), -4.39150654e-06f);
        p = __fadd_rn(__fmul_rn(p, w),  0.00021858087f);
        p = __fadd_rn(__fmul_rn(p, w), -0.00125372503f);
        p = __fadd_rn(__fmul_rn(p, w), -0.00417768164f);
        p = __fadd_rn(__fmul_rn(p, w),  0.246640727f);
        p = __fadd_rn(__fmul_rn(p, w),  1.50140941f);
    } else {
        w = __fsub_rn(__fsqrt_rn(w), 3.0f);
        p = -0.000200214257f;
        p = __fadd_rn(__fmul_rn(p, w),  0.000100950558f);
        p = __fadd_rn(__fmul_rn(p, w),  0.00134934322f);
        p = __fadd_rn(__fmul_rn(p, w), -0.00367342844f);
        p = __fadd_rn(__fmul_rn(p, w),  0.00573950773f);
        p = __fadd_rn(__fmul_rn(p, w), -0.0076224613f);
        p = __fadd_rn(__fmul_rn(p, w),  0.00943887047f);
        p = __fadd_rn(__fmul_rn(p, w),  1.00167406f);
        p = __fadd_rn(__fmul_rn(p, w),  2.83297682f);
    }
    return __fmul_rn(p, x);
}

// ---------------------------------------------------------------------------
// Phase A (R2): warp-per-row masked mean embedding + input linear.
//   - lane-strided coalesced token loads
//   - per-lane gather of 64B embedding rows via 4x float4 (high MLP)
//   - 16 independent f32 accumulators, 5-level butterfly reduction
//   - 64x16 dot via fmaf with Wc staged in shared
// ---------------------------------------------------------------------------
__global__ void __launch_bounds__(256)
phaseA_kernel(const int* __restrict__ tokens,
              const float* __restrict__ embed,
              const float* __restrict__ Wc,
              const float* __restrict__ bc,
              float* __restrict__ cur, int B, int L) {
    __shared__ float sWc[HIDDEN * EMBED];   // 4 KB
    __shared__ float sbc[HIDDEN];

    int tid = threadIdx.x;
    for (int i = tid; i < HIDDEN * EMBED; i += 256) sWc[i] = Wc[i];
    if (tid < HIDDEN) sbc[tid] = bc[tid];
    __syncthreads();

    int warp = (blockIdx.x * 256 + tid) >> 5;
    int lane = tid & 31;
    if (warp >= B) return;

    const int* trow = tokens + (size_t)warp * L;

    float a0=0,a1=0,a2=0,a3=0,a4=0,a5=0,a6=0,a7=0;
    float a8=0,a9=0,a10=0,a11=0,a12=0,a13=0,a14=0,a15=0;
    int cnt = 0;

    for (int j = lane; j < L; j += 32) {
        int tk = __ldg(trow + j);
        if (tk != 0) {
            const float4* e = (const float4*)(embed + (size_t)tk * EMBED);
            float4 p = __ldg(e + 0);
            float4 q = __ldg(e + 1);
            float4 r = __ldg(e + 2);
            float4 s = __ldg(e + 3);
            a0 += p.x; a1 += p.y; a2  += p.z; a3  += p.w;
            a4 += q.x; a5 += q.y; a6  += q.z; a7  += q.w;
            a8 += r.x; a9 += r.y; a10 += r.z; a11 += r.w;
            a12+= s.x; a13+= s.y; a14 += s.z; a15 += s.w;
            cnt++;
        }
    }

    // butterfly reduce (all lanes end with totals)
    #pragma unroll
    for (int o = 16; o; o >>= 1) {
        a0  += __shfl_xor_sync(0xffffffffu, a0,  o);
        a1  += __shfl_xor_sync(0xffffffffu, a1,  o);
        a2  += __shfl_xor_sync(0xffffffffu, a2,  o);
        a3  += __shfl_xor_sync(0xffffffffu, a3,  o);
        a4  += __shfl_xor_sync(0xffffffffu, a4,  o);
        a5  += __shfl_xor_sync(0xffffffffu, a5,  o);
        a6  += __shfl_xor_sync(0xffffffffu, a6,  o);
        a7  += __shfl_xor_sync(0xffffffffu, a7,  o);
        a8  += __shfl_xor_sync(0xffffffffu, a8,  o);
        a9  += __shfl_xor_sync(0xffffffffu, a9,  o);
        a10 += __shfl_xor_sync(0xffffffffu, a10, o);
        a11 += __shfl_xor_sync(0xffffffffu, a11, o);
        a12 += __shfl_xor_sync(0xffffffffu, a12, o);
        a13 += __shfl_xor_sync(0xffffffffu, a13, o);
        a14 += __shfl_xor_sync(0xffffffffu, a14, o);
        a15 += __shfl_xor_sync(0xffffffffu, a15, o);
        cnt += __shfl_xor_sync(0xffffffffu, cnt, o);
    }

    float inv = __fdiv_rn(1.0f, fmaxf((float)cnt, 1.0f));
    float avg[EMBED] = {
        a0*inv, a1*inv, a2*inv, a3*inv, a4*inv, a5*inv, a6*inv, a7*inv,
        a8*inv, a9*inv, a10*inv, a11*inv, a12*inv, a13*inv, a14*inv, a15*inv };

    // each lane computes 2 hidden outputs
    #pragma unroll
    for (int r = 0; r < 2; r++) {
        int h = lane + 32 * r;
        const float* wrow = &sWc[h * EMBED];
        float d = 0.0f;
        #pragma unroll
        for (int q = 0; q < EMBED; q++) d = fmaf(avg[q], wrow[q], d);
        cur[(size_t)warp * HIDDEN + h] = __fadd_rn(d, sbc[h]);
    }
}

// ---------------------------------------------------------------------------
// Phase B: 10-tick stochastic spiking recurrence. One thread per neuron.
// ---------------------------------------------------------------------------
struct KeysParam { uint32_t kn0[TICKS], kn1[TICKS], kf0[TICKS], kf1[TICKS]; };

__global__ void __launch_bounds__(256)
phaseB_kernel(const float* __restrict__ cur, float* __restrict__ spk_out,
              KeysParam K, int n, int use_global_fallback) {
    int i = blockIdx.x * blockDim.x + threadIdx.x;
    if (i >= n) return;
    float* outp = use_global_fallback ? g_spk : spk_out;

    float cu = cur[i];
    float v = 0.0f, rf = 0.0f, acc = 0.0f;
    uint32_t ui = (uint32_t)i;
    const float LO = -0.99999994f;

    #pragma unroll
    for (int t = 0; t < TICKS; t++) {
        uint32_t n0, n1, f0, f1;
        tf2x32_dev(K.kn0[t], K.kn1[t], 0u, ui, n0, n1);
        tf2x32_dev(K.kf0[t], K.kf1[t], 0u, ui, f0, f1);
        uint32_t nb = n0 ^ n1;
        uint32_t fb = f0 ^ f1;

        float fr = __fsub_rn(__uint_as_float((nb >> 9) | 0x3f800000u), 1.0f);
        float u  = fmaxf(LO, __fadd_rn(__fmul_rn(fr, 2.0f), LO));
        float z  = erfinv_xla(u);
        float noise = __fmul_rn(0.01f, __fmul_rn(1.41421356237309515f, z));

        v = __fadd_rn(__fadd_rn(__fmul_rn(v, 0.98f), cu), noise);

        float uf = __fsub_rn(__uint_as_float((fb >> 9) | 0x3f800000u), 1.0f);
        bool fire = (__fsub_rn(v, rf) > 0.5f) && (uf >= 0.5f);
        float spike = fire ? 1.0f : 0.0f;
        v  = fire ? 0.0f : v;
        rf = __fadd_rn(__fmul_rn(rf, 0.95f), spike);
        acc = __fadd_rn(acc, spike);
    }
    outp[i] = __fdiv_rn(acc, 10.0f);
}

// ---------------------------------------------------------------------------
// Phase C: logits = avg_spikes @ Wr.T + br   (one warp per row)
// ---------------------------------------------------------------------------
__global__ void phaseC_kernel(const float* __restrict__ spk_in,
                              const float* __restrict__ Wr,
                              const float* __restrict__ br,
                              float* __restrict__ logits, int B,
                              int use_global_fallback) {
    const float* spk = use_global_fallback ? g_spk : spk_in;
    int gw   = (blockIdx.x * blockDim.x + threadIdx.x) >> 5;
    int lane = threadIdx.x & 31;
    if (gw >= B) return;
    float s0 = spk[gw * HIDDEN + lane];
    float s1 = spk[gw * HIDDEN + 32 + lane];
    #pragma unroll
    for (int cc = 0; cc < 4; cc++) {
        float p = __fadd_rn(__fmul_rn(s0, Wr[cc * HIDDEN + lane]),
                            __fmul_rn(s1, Wr[cc * HIDDEN + 32 + lane]));
        #pragma unroll
        for (int o = 16; o; o >>= 1)
            p = __fadd_rn(p, __shfl_xor_sync(0xffffffffu, p, o));
        if (lane == 0) logits[gw * 4 + cc] = __fadd_rn(p, br[cc]);
    }
}

// ---------------------------------------------------------------------------
extern "C" void kernel_launch(void* const* d_in, const int* in_sizes, int n_in,
                              void* d_out, int out_size) {
    const int*   tokens = (const int*)d_in[0];
    const float* embed  = (const float*)d_in[1];
    const float* Wc     = (const float*)d_in[2];
    const float* bc     = (const float*)d_in[3];
    const float* Wr     = (const float*)d_in[4];
    const float* br     = (const float*)d_in[5];

    int L = SEQLEN;
    int B = in_sizes[0] / L;
    int n = B * HIDDEN;

    KeysParam K;
    for (int t = 0; t < TICKS; t++) {
        uint32_t kt0, kt1;
        tf2x32_host(0u, 1u, 0u, (uint32_t)t, &kt0, &kt1);
        tf2x32_host(kt0, kt1, 0u, 0u, &K.kn0[t], &K.kn1[t]);
        tf2x32_host(kt0, kt1, 0u, 1u, &K.kf0[t], &K.kf1[t]);
    }

    float* out_f = (float*)d_out;
    int need = B * 4 + B * HIDDEN;
    int fallback = (out_size < need) ? 1 : 0;
    float* spk_region = fallback ? (float*)nullptr : (out_f + B * 4);

    void* cur_ptr = nullptr;
    cudaGetSymbolAddress(&cur_ptr, g_cur);

    int warpsA = B;                       // one warp per row
    int blocksA = (warpsA * 32 + 255) / 256;
    phaseA_kernel<<<blocksA, 256>>>(tokens, embed, Wc, bc, (float*)cur_ptr, B, L);

    phaseB_kernel<<<(n + 255) / 256, 256>>>((const float*)cur_ptr,
                                            spk_region, K, n, fallback);

    phaseC_kernel<<<(B * 32 + 255) / 256, 256>>>(spk_region, Wr, br,
                                                 out_f, B, fallback);
}